// round 1
// baseline (speedup 1.0000x reference)
#include <cuda_runtime.h>
#include <stdint.h>

// TRFAligner: out[b,c,t] = sum_{s,w: idx[b,s]+w == t, t < N} TRFs[b,c,w,s]
// Shapes: B=4, C=64, W=64, S=4096, N=32768. idx sorted strictly increasing per b.

#define BB 4
#define CC 64
#define WW 64
#define SS 4096
#define NN 32768

#define NS     64    // segments per chunk (64 chunks per batch)
#define CG     2     // channels per CTA (32 channel-groups)
#define NSTOT  127   // max staged segments = NS + 63 (left halo bounded by idx distinctness)
#define NTHREADS 512

__global__ __launch_bounds__(NTHREADS)
void trf_align_kernel(const float* __restrict__ trfg,
                      const int*   __restrict__ ig32,   // int32 view of sourceIdx
                      float* __restrict__ out)
{
    extern __shared__ float smem[];
    float* trf  = smem;                                  // [CG*WW][NSTOT]
    int*   idxL = (int*)(smem + CG * WW * NSTOT);        // [NSTOT]
    __shared__ int sh_sLo, sh_n, sh_ownLo, sh_ownHi, sh_stride;

    const int chunk = blockIdx.x;   // 0..63
    const int cg    = blockIdx.y;   // 0..31
    const int b     = blockIdx.z;   // 0..3
    const int s0    = chunk * NS;
    const int cbase = cg * CG;
    const int tid   = threadIdx.x;

    if (tid == 0) {
        // Sniff dtype of sourceIdx: if int64, high word of element 0 is 0.
        // If int32, this word is idx[b=0][1] >= 1 (strictly increasing, nonneg).
        int stride = (ig32[1] == 0) ? 2 : 1;
        sh_stride = stride;
        const int base = b * SS;
        int Pk = ig32[(base + s0) * stride];
        int sLo = s0;
        while (sLo > 0 && ig32[(base + sLo - 1) * stride] >= Pk - 63) sLo--;
        int s1 = s0 + NS;
        sh_sLo   = sLo;
        sh_n     = s1 - sLo;
        sh_ownLo = (chunk == 0) ? 0 : Pk;
        sh_ownHi = (s1 >= SS) ? NN : ig32[(base + s1) * stride];
    }
    __syncthreads();
    const int sLo = sh_sLo, n = sh_n, ownLo = sh_ownLo, ownHi = sh_ownHi;
    const int estr = sh_stride;

    // Load staged idx values (relative-absolute positions, < 32768 -> int ok)
    for (int j = tid; j < n; j += NTHREADS)
        idxL[j] = ig32[(b * SS + sLo + j) * estr];

    // Stage TRF tile: rows = (c,w), cols = staged s (coalesced global reads)
    {
        const int warp = tid >> 5, lane = tid & 31;
        for (int row = warp; row < CG * WW; row += NTHREADS / 32) {
            const int c = row >> 6;          // 0..CG-1
            const int w = row & 63;
            const float* src = trfg +
                (((size_t)((b * CC + cbase + c) * WW + w)) * SS + sLo);
            float* dst = trf + row * NSTOT;
            for (int j = lane; j < n; j += 32)
                dst[j] = src[j];
        }
    }
    __syncthreads();

    // Gather: each thread owns output positions t (exclusive across CTAs -> plain STG)
    const size_t ob = (size_t)(b * CC + cbase) * NN;
    for (int t = ownLo + tid; t < ownHi; t += NTHREADS) {
        // hi = upper_bound(idxL, t): count of staged idx <= t
        int lo_ = 0, hi_ = n;
        while (lo_ < hi_) {
            int mid = (lo_ + hi_) >> 1;
            if (idxL[mid] <= t) lo_ = mid + 1; else hi_ = mid;
        }
        float a0 = 0.f, a1 = 0.f;
        const int tmin = t - 63;
        for (int s = lo_ - 1; s >= 0; --s) {
            const int p = idxL[s];
            if (p < tmin) break;
            const int w = t - p;
            a0 += trf[w * NSTOT + s];
            a1 += trf[(WW + w) * NSTOT + s];
        }
        out[ob + t]      = a0;
        out[ob + NN + t] = a1;
    }
}

extern "C" void kernel_launch(void* const* d_in, const int* in_sizes, int n_in,
                              void* d_out, int out_size)
{
    const float* trfg = (const float*)d_in[0];
    const int*   ig32 = (const int*)d_in[1];   // works for int32 or int64 (sniffed on device)
    float* out = (float*)d_out;

    const size_t smemBytes = (size_t)CG * WW * NSTOT * sizeof(float)
                           + NSTOT * sizeof(int) + 16;

    cudaFuncSetAttribute(trf_align_kernel,
                         cudaFuncAttributeMaxDynamicSharedMemorySize,
                         (int)smemBytes);

    dim3 grid(SS / NS, CC / CG, BB);   // (64, 32, 4)
    trf_align_kernel<<<grid, NTHREADS, smemBytes>>>(trfg, ig32, out);
}

// round 3
// speedup vs baseline: 1.0401x; 1.0401x over previous
#include <cuda_runtime.h>
#include <cuda_fp16.h>
#include <stdint.h>

// TRFAligner: out[b,c,t] = sum_{s,w: idx[b,s]+w == t, t < N} TRFs[b,c,w,s]
// B=4, C=64, W=64, S=4096, N=32768. idx sorted strictly increasing per b.
// Ownership gather: chunk k of NS segments exclusively owns t in [idx[s0], idx[s0+NS]),
// extended to [0,..) for chunk 0 and [..,N) for the last -> plain STG, no atomics.

#define BB 4
#define CC 64
#define WW 64
#define SS 4096
#define NN 32768

#define NS       64            // segments per chunk
#define CG       4             // channels per CTA
#define NROWS    (CG * WW)     // 256 staged rows
#define NSTOT    130           // padded staged-segment capacity (max needed 127)
#define NPAIR    (NSTOT / 2)   // 65 half2 per row
#define WIN      128           // idx window: s0-63 .. s0+NS
#define NTHREADS 512

__global__ __launch_bounds__(NTHREADS)
void trf_align_kernel(const float* __restrict__ trfg,
                      const int*   __restrict__ ig32,   // int32 view of sourceIdx
                      float* __restrict__ out)
{
    extern __shared__ __align__(16) char smem_raw[];
    __half* trf  = (__half*)smem_raw;                       // [NROWS][NSTOT]
    int*    idxW = (int*)(smem_raw + NROWS * NSTOT * 2);    // [WIN]
    __shared__ int sh_minK;

    const int chunk = blockIdx.x;   // 0..63
    const int cg    = blockIdx.y;   // 0..15
    const int b     = blockIdx.z;   // 0..3
    const int s0    = chunk * NS;
    const int s1    = s0 + NS;                 // <= SS always
    const int cbase = cg * CG;
    const int tid   = threadIdx.x;
    const int wid   = tid >> 5;
    const int lane  = tid & 31;

    // dtype sniff: int64 -> word 1 is high half of idx[0][0] == 0;
    // int32 -> word 1 is idx[0][1] >= 1 (strictly increasing, nonneg).
    const int estr = (ig32[1] == 0) ? 2 : 1;

    // ---- parallel preamble: load idx window [s0-63, s0+NS] into smem ----
    if (tid == 0) sh_minK = 63;
    if (tid < WIN) {
        int s = s0 - 63 + tid;
        int v;
        if (s < 0)        v = -1000000;        // sentinel: halo cond false
        else if (s >= SS) v = NN;              // only k=127 at last chunk
        else              v = ig32[(b * SS + s) * estr];
        idxW[tid] = v;
    }
    __syncthreads();

    const int Pk = idxW[63];                   // idx[s0]
    // halo start: min k in [0,63] with idxW[k] >= Pk-63 (monotone; k=63 always true)
    if (tid < 63 && idxW[tid] >= Pk - 63) atomicMin(&sh_minK, tid);
    __syncthreads();

    const int minK  = sh_minK;
    const int sLo   = s0 - 63 + minK;
    const int n     = s1 - sLo;                // <= 127
    const int*  idxL = idxW + minK;            // idxL[j] = idx[sLo + j]
    const int ownLo = (chunk == 0) ? 0 : Pk;
    const int ownHi = (s1 >= SS) ? NN : idxW[WIN - 1];

    // ---- stage TRF tile as fp16: rows=(c,w), cols=staged s (coalesced LDG) ----
    {
        const int npairs  = (n + 1) >> 1;
        const size_t gRow = (size_t)((b * CC + cbase) * WW) * SS + sLo;
        __half2* h2 = (__half2*)trf;
        #pragma unroll 4
        for (int e = tid; e < NROWS * 64; e += NTHREADS) {
            const int row = e >> 6;
            const int jp  = e & 63;
            if (jp < npairs) {
                const int j = jp * 2;
                const float* src = trfg + gRow + (size_t)row * SS;
                float f0 = src[j];
                float f1 = (j + 1 < n) ? src[j + 1] : 0.0f;
                h2[row * NPAIR + jp] = __floats2half2_rn(f0, f1);
            }
        }
    }
    __syncthreads();

    // ---- gather: warp-uniform upper-bound search, per-lane walk ----
    const size_t ob = (size_t)(b * CC + cbase) * NN;
    for (int t0 = ownLo + wid * 32; t0 < ownHi; t0 += NTHREADS) {
        const int tHi = min(t0 + 31, ownHi - 1);
        // upper_bound(tHi): uniform across warp -> broadcast LDS
        int lo = 0, hi = n;
        while (lo < hi) {
            int mid = (lo + hi) >> 1;
            if (idxL[mid] <= tHi) lo = mid + 1; else hi = mid;
        }
        const int t = t0 + lane;
        if (t < ownHi) {
            const int tmin = t - 63;
            float a0 = 0.f, a1 = 0.f, a2 = 0.f, a3 = 0.f;
            for (int s = lo - 1; s >= 0; --s) {
                const int p = idxL[s];
                if (p < tmin) break;
                // branchless skip of entries with p in (t, tHi] (other lanes' segs)
                const bool ok = (p <= t);
                const int off = ok ? ((t - p) * NSTOT + s) : s;  // w=0 dummy read
                const float m = ok ? 1.0f : 0.0f;
                a0 += m * __half2float(trf[off]);
                a1 += m * __half2float(trf[off + 1 * WW * NSTOT]);
                a2 += m * __half2float(trf[off + 2 * WW * NSTOT]);
                a3 += m * __half2float(trf[off + 3 * WW * NSTOT]);
            }
            out[ob + t]          = a0;
            out[ob + NN + t]     = a1;
            out[ob + 2 * NN + t] = a2;
            out[ob + 3 * NN + t] = a3;
        }
    }
}

extern "C" void kernel_launch(void* const* d_in, const int* in_sizes, int n_in,
                              void* d_out, int out_size)
{
    const float* trfg = (const float*)d_in[0];
    const int*   ig32 = (const int*)d_in[1];
    float* out = (float*)d_out;

    const size_t smemBytes = (size_t)NROWS * NSTOT * sizeof(__half)
                           + WIN * sizeof(int) + 32;

    cudaFuncSetAttribute(trf_align_kernel,
                         cudaFuncAttributeMaxDynamicSharedMemorySize,
                         (int)smemBytes);

    dim3 grid(SS / NS, CC / CG, BB);   // (64, 16, 4)
    trf_align_kernel<<<grid, NTHREADS, smemBytes>>>(trfg, ig32, out);
}

// round 5
// speedup vs baseline: 2.0013x; 1.9240x over previous
#include <cuda_runtime.h>
#include <cuda_fp16.h>
#include <stdint.h>

// TRFAligner: out[b,c,t] = sum_{s,w: idx[b,s]+w == t, t < N} TRFs[b,c,w,s]
// B=4, C=64, W=64, S=4096, N=32768. idx sorted strictly increasing per b.
// Ownership gather: chunk k of NS segments exclusively owns t in [idx[s0], idx[s0+NS]),
// extended to [0,..) for chunk 0 and [..,N) for the last -> plain STG, no atomics.

#define BB 4
#define CC 64
#define WW 64
#define SS 4096
#define NN 32768

#define NS       64            // segments per chunk
#define CG       4             // channels per CTA
#define RSTRIDE  129           // s-stride per w row (odd -> conflict-free LDS.64)
#define WIN      129           // idx window: s0-64 .. s0+NS   (extra left slot: see minK>=1 proof)
#define NTHREADS 512

__device__ __forceinline__ __half2 f_as_h2(float f)
{
    unsigned u = __float_as_uint(f);
    return *reinterpret_cast<__half2*>(&u);
}

__global__ __launch_bounds__(NTHREADS)
void trf_align_kernel(const float* __restrict__ trfg,
                      const int*   __restrict__ ig32,   // int32 view of sourceIdx
                      float* __restrict__ out)
{
    extern __shared__ __align__(16) char smem_raw[];
    // tile: halfs, layout index = (w*RSTRIDE + s)*CG + c   (c fastest)
    __half2* h2 = (__half2*)smem_raw;                    // half2 idx = (w*RSTRIDE+s)*2 + cp
    int* idxW = (int*)(smem_raw + (size_t)WW * RSTRIDE * CG * 2);  // [WIN]
    __shared__ int sh_minK;

    const int chunk = blockIdx.x;   // 0..63
    const int cg    = blockIdx.y;   // 0..15
    const int b     = blockIdx.z;   // 0..3
    const int s0    = chunk * NS;
    const int s1    = s0 + NS;
    const int cbase = cg * CG;
    const int tid   = threadIdx.x;
    const int wid   = tid >> 5;
    const int lane  = tid & 31;

    // dtype sniff: int64 -> word 1 is high half of idx[0][0] == 0;
    // int32 -> word 1 is idx[0][1] >= 1 (strictly increasing, nonneg).
    const int estr = (ig32[1] == 0) ? 2 : 1;

    // ---- parallel preamble: idx window [s0-64, s0+NS] -> smem ----
    if (tid == 0) sh_minK = 64;
    if (tid < WIN) {
        int s = s0 - 64 + tid;
        int v;
        if (s < 0)        v = -1000000;       // halo predicate false
        else if (s >= SS) v = NN;             // only index 128 at last chunk
        else              v = ig32[(b * SS + s) * estr];
        idxW[tid] = v;
    }
    __syncthreads();

    const int Pk = idxW[64];                  // idx[s0]
    // min k in [1,64] with idxW[k] >= Pk-63 (monotone; k=64 always true).
    // k=0 can never qualify: 64 strictly-increasing steps span >= 64, so
    // idx[s0-64] <= Pk-64 < Pk-63  =>  minK >= 1 always.
    if (tid >= 1 && tid < 64 && idxW[tid] >= Pk - 63) atomicMin(&sh_minK, tid);
    __syncthreads();

    int sLo = s0 - 64 + sh_minK;
    if (sLo & 1) sLo--;                       // even for LDG.64 staging; stays >= s0-64
    const int n     = s1 - sLo;               // even, <= 128
    const int* idxL = idxW + (sLo - (s0 - 64)); // idxL[j] = idx[sLo+j]; idxL[n] valid (==idxW[128] max)
    const int ownLo = (chunk == 0) ? 0 : Pk;
    const int ownHi = (s1 >= SS) ? NN : idxW[WIN - 1];

    // ---- stage tile fp16, channel-interleaved [w][s][c] ----
    {
        const int npairs = n >> 1;            // <= 64
        const size_t g0 = ((size_t)(b * CC + cbase) * WW) * SS + sLo;
        #pragma unroll 4
        for (int e = tid; e < 2 * WW * 64; e += NTHREADS) {
            const int jp = e & 63;            // s-pair index
            const int w  = (e >> 6) & 63;
            const int cp = e >> 12;           // channel pair 0..1
            if (jp < npairs) {
                const int j = jp * 2;
                const float* r0 = trfg + g0 + ((size_t)(2 * cp) * WW + w) * SS;
                const float2 f0 = *(const float2*)(r0 + j);                    // chan 2cp
                const float2 f1 = *(const float2*)(r0 + (size_t)WW * SS + j);  // chan 2cp+1
                h2[(w * RSTRIDE + j) * 2 + cp]     = __floats2half2_rn(f0.x, f1.x);
                h2[(w * RSTRIDE + j + 1) * 2 + cp] = __floats2half2_rn(f0.y, f1.y);
            }
        }
    }
    __syncthreads();

    // ---- gather: uniform segment loop, shfl-broadcast p, LDS.64 per (w,s) ----
    const size_t ob = (size_t)(b * CC + cbase) * NN;
    for (int t0 = ownLo + wid * 32; t0 < ownHi; t0 += NTHREADS) {
        // jHi = #p <= t0+31, jLo = #p <= t0-64 : fixed-step branchless gallops
        int jHi = 0, jLo = 0;
        const int keyH = t0 + 31, keyL = t0 - 64;
        #pragma unroll
        for (int k = 128; k >= 1; k >>= 1) {
            if (jHi + k <= n && idxL[jHi + k - 1] <= keyH) jHi += k;
            if (jLo + k <= n && idxL[jLo + k - 1] <= keyL) jLo += k;
        }
        const int t    = t0 + lane;
        const bool tok = (t < ownHi);
        float a0 = 0.f, a1 = 0.f, a2 = 0.f, a3 = 0.f;

        for (int base = jLo; base < jHi; base += 32) {
            const int j  = base + lane;
            const int pj = (j < jHi) ? idxL[j < n ? j : n] : 0x7fffffff;
            const int m  = min(32, jHi - base);
            for (int k = 0; k < m; k++) {
                const int p = __shfl_sync(0xffffffffu, pj, k);
                const unsigned w = (unsigned)(t - p);
                const bool ok = tok && (w < 64u);
                const int hoff = ok ? ((int)w * RSTRIDE + base + k) * 2 : 0;
                const float2 raw = *(const float2*)(h2 + hoff);   // LDS.64: 4 halfs
                const float2 f01 = __half22float2(f_as_h2(raw.x));
                const float2 f23 = __half22float2(f_as_h2(raw.y));
                const float mm = ok ? 1.0f : 0.0f;
                a0 += mm * f01.x; a1 += mm * f01.y;
                a2 += mm * f23.x; a3 += mm * f23.y;
            }
        }
        if (tok) {
            out[ob + t]          = a0;
            out[ob + NN + t]     = a1;
            out[ob + 2 * NN + t] = a2;
            out[ob + 3 * NN + t] = a3;
        }
    }
}

extern "C" void kernel_launch(void* const* d_in, const int* in_sizes, int n_in,
                              void* d_out, int out_size)
{
    const float* trfg = (const float*)d_in[0];
    const int*   ig32 = (const int*)d_in[1];
    float* out = (float*)d_out;

    const size_t smemBytes = (size_t)WW * RSTRIDE * CG * 2   // fp16 tile (~66 KB)
                           + WIN * sizeof(int) + 32;

    cudaFuncSetAttribute(trf_align_kernel,
                         cudaFuncAttributeMaxDynamicSharedMemorySize,
                         (int)smemBytes);

    dim3 grid(SS / NS, CC / CG, BB);   // (64, 16, 4)
    trf_align_kernel<<<grid, NTHREADS, smemBytes>>>(trfg, ig32, out);
}